// round 8
// baseline (speedup 1.0000x reference)
#include <cuda_runtime.h>
#include <cstdint>

// Problem constants (fixed by dataset): B=262144, D=32, R=16
#define R 16
#define BATCH_MAX 262144

// Bit layout (bit i = X[b][i]):
//   bits 0..9   -> U table (1024): e_{x0}*F * M0..M8
//   bits 10..21 -> 4 mid groups of 3 bits: T_k = M_{9+3k}*M_{10+3k}*M_{11+3k}
//   bits 22..31 -> W table (1024): M21..M29 * last_{x31}
// Per batch: v = U[j0]; v = v @ T_k[idx_k] (k=0..3); out = dot(v, W[j1])
//
// Batches are bucket-sorted by the 12-bit mid key so warp lanes share the
// same mid matrices -> LDS broadcasts (16B served instead of 512B).
// Mid matrices at stride 260 floats: conflict-free for mixed idx anyway.

__device__ float              g_U[1024 * 16];
__device__ float              g_T[4 * 8 * 256];
__device__ float              g_W[1024 * 16];
__device__ unsigned           g_masks[BATCH_MAX];
__device__ unsigned           g_hist[4096];
__device__ unsigned           g_binptr[4096];
__device__ unsigned long long g_sorted[BATCH_MAX];   // (origIdx<<32)|mask

// ---------------------------------------------------------------------------
// Packed f32x2 helpers (sm_103a FFMA2 — only reachable via PTX fma.rn.f32x2)
// ---------------------------------------------------------------------------
__device__ __forceinline__ unsigned long long pack2(float a, float b) {
    unsigned long long r;
    asm("mov.b64 %0, {%1, %2};" : "=l"(r) : "f"(a), "f"(b));
    return r;
}
__device__ __forceinline__ void unpack2(unsigned long long p, float& a, float& b) {
    asm("mov.b64 {%0, %1}, %2;" : "=f"(a), "=f"(b) : "l"(p));
}
__device__ __forceinline__ unsigned long long ffma2(unsigned long long a,
                                                    unsigned long long b,
                                                    unsigned long long c) {
    unsigned long long d;
    asm("fma.rn.f32x2 %0, %1, %2, %3;" : "=l"(d) : "l"(a), "l"(b), "l"(c));
    return d;
}
__device__ __forceinline__ unsigned long long fmul2(unsigned long long a,
                                                    unsigned long long b) {
    unsigned long long d;
    asm("mul.rn.f32x2 %0, %1, %2;" : "=l"(d) : "l"(a), "l"(b));
    return d;
}
__device__ __forceinline__ unsigned long long fadd2(unsigned long long a,
                                                    unsigned long long b) {
    unsigned long long d;
    asm("add.rn.f32x2 %0, %1, %2;" : "=l"(d) : "l"(a), "l"(b));
    return d;
}

// ---------------------------------------------------------------------------
__global__ void zero_hist() {
    g_hist[blockIdx.x * 1024 + threadIdx.x] = 0u;
}

// ---------------------------------------------------------------------------
// Prep kernel: mask pack + fused 12-bit-key histogram + table builders.
//   blocks [0, packB)        : 8 warps x 32 rows each, coalesced ballot pack
//   blocks [packB, +64)      : U entries
//   blocks [packB+64, +128)  : W entries
//   blocks [packB+128, +132) : T group k
// ---------------------------------------------------------------------------
__global__ void prep(const int* __restrict__ X,
                     const float* __restrict__ cf,
                     const float* __restrict__ cm,
                     const float* __restrict__ cl,
                     int packB) {
    int bid = blockIdx.x;
    if (bid < packB) {
        int warp = threadIdx.x >> 5;
        int lane = threadIdx.x & 31;
        int base = (bid * 8 + warp) * 32;
        const int* xb = X + (long long)base * 32 + lane;
        unsigned mask = 0;
        #pragma unroll
        for (int h = 0; h < 4; h++) {
            int t[8];
            #pragma unroll
            for (int i = 0; i < 8; i++) t[i] = xb[(h * 8 + i) * 32];
            #pragma unroll
            for (int i = 0; i < 8; i++) {
                unsigned bm = __ballot_sync(0xffffffffu, t[i]);
                if (lane == h * 8 + i) mask = bm;
            }
        }
        g_masks[base + lane] = mask;
        atomicAdd(&g_hist[(mask >> 10) & 4095u], 1u);
        return;
    }
    bid -= packB;
    if (bid < 64) {
        // U[j][s] = (e_{x0} F) * M_{0,b1} * ... * M_{8,b9}
        int gwarp = (bid * 256 + threadIdx.x) >> 5;   // 0..511
        int lane  = threadIdx.x & 31;
        int half  = lane >> 4;
        int s     = lane & 15;
        int j     = gwarp * 2 + half;                 // 0..1023
        float v = cf[s * 2 + (j & 1)];
        for (int i = 0; i < 9; i++) {
            int b = (j >> (i + 1)) & 1;
            float nv = 0.f;
            #pragma unroll
            for (int r = 0; r < 16; r++) {
                float vr = __shfl_sync(0xffffffffu, v, (half << 4) + r);
                nv += vr * cm[((i * 16 + r) * 16 + s) * 2 + b];
            }
            v = nv;
        }
        g_U[j * 16 + s] = v;
    } else if (bid < 128) {
        // W[j][r] = (M_{21,b0} * ... * M_{29,b8} * lastcol_{b9})[r]
        int gwarp = ((bid - 64) * 256 + threadIdx.x) >> 5;
        int lane  = threadIdx.x & 31;
        int half  = lane >> 4;
        int r     = lane & 15;
        int j     = gwarp * 2 + half;
        float v = cl[r * 2 + ((j >> 9) & 1)];
        for (int i = 8; i >= 0; i--) {
            int c = 21 + i;
            int b = (j >> i) & 1;
            float nv = 0.f;
            #pragma unroll
            for (int t = 0; t < 16; t++) {
                float vt = __shfl_sync(0xffffffffu, v, (half << 4) + t);
                nv += cm[((c * 16 + r) * 16 + t) * 2 + b] * vt;
            }
            v = nv;
        }
        g_W[j * 16 + r] = v;
    } else {
        // T_k[idx] = M_{9+3k,b0} * M_{10+3k,b1} * M_{11+3k,b2}
        if (threadIdx.x >= 128) return;
        int k   = bid - 128;
        int idx = threadIdx.x >> 4;
        int s   = threadIdx.x & 15;
        float v[R], nv[R];
        int c2 = 9 + 3 * k + 2;
        int b2 = (idx >> 2) & 1;
        #pragma unroll
        for (int t = 0; t < R; t++) v[t] = cm[((c2 * R + t) * R + s) * 2 + b2];
        for (int jj = 1; jj >= 0; jj--) {
            int c = 9 + 3 * k + jj;
            int b = (idx >> jj) & 1;
            #pragma unroll
            for (int r = 0; r < R; r++) {
                float acc = 0.f;
                #pragma unroll
                for (int t = 0; t < R; t++)
                    acc += cm[((c * R + r) * R + t) * 2 + b] * v[t];
                nv[r] = acc;
            }
            #pragma unroll
            for (int r = 0; r < R; r++) v[r] = nv[r];
        }
        #pragma unroll
        for (int r = 0; r < R; r++)
            g_T[(k * 8 + idx) * 256 + r * R + s] = v[r];
    }
}

// ---------------------------------------------------------------------------
// Exclusive scan of the 4096-bin histogram (single block, 1024 threads).
// ---------------------------------------------------------------------------
__global__ void scan_hist() {
    __shared__ unsigned tot[1024];
    int t = threadIdx.x;
    unsigned v0 = g_hist[t * 4 + 0];
    unsigned v1 = g_hist[t * 4 + 1];
    unsigned v2 = g_hist[t * 4 + 2];
    unsigned v3 = g_hist[t * 4 + 3];
    unsigned s1 = v0 + v1, s2 = s1 + v2, s3 = s2 + v3;
    tot[t] = s3;
    __syncthreads();
    for (int off = 1; off < 1024; off <<= 1) {
        unsigned add = (t >= off) ? tot[t - off] : 0u;
        __syncthreads();
        tot[t] += add;
        __syncthreads();
    }
    unsigned excl = (t == 0) ? 0u : tot[t - 1];
    g_binptr[t * 4 + 0] = excl;
    g_binptr[t * 4 + 1] = excl + v0;
    g_binptr[t * 4 + 2] = excl + s1;
    g_binptr[t * 4 + 3] = excl + s2;
}

// ---------------------------------------------------------------------------
// Scatter batches into key-sorted order. Within-bucket order is atomic-race
// nondeterministic but each batch's result is computed independently and
// written to its original slot, so the OUTPUT is deterministic.
// ---------------------------------------------------------------------------
__global__ void scatter() {
    int i = blockIdx.x * 256 + threadIdx.x;
    unsigned m = g_masks[i];
    unsigned key = (m >> 10) & 4095u;
    unsigned pos = atomicAdd(&g_binptr[key], 1u);
    g_sorted[pos] = ((unsigned long long)(unsigned)i << 32) | (unsigned long long)m;
}

// ---------------------------------------------------------------------------
// Main kernel: 512 threads/block, 1 block/SM (smem) -> 108 regs, no spills.
// Lanes take consecutive key-sorted entries -> mid-table LDS are broadcasts.
// ---------------------------------------------------------------------------
#define T_STRIDE 260
#define UW_STRIDE 20
#define ST_FLOATS (4 * 8 * T_STRIDE)
#define SUW_FLOATS (1024 * UW_STRIDE)
#define SMEM_FLOATS (ST_FLOATS + 2 * SUW_FLOATS)
#define SMEM_BYTES (SMEM_FLOATS * 4)

extern __shared__ float sm_buf[];

__global__ __launch_bounds__(512, 1) void tt_main(float* __restrict__ out, int B) {
    float* sT = sm_buf;
    float* sU = sm_buf + ST_FLOATS;
    float* sW = sU + SUW_FLOATS;

    for (int i = threadIdx.x; i < 4 * 8 * 256; i += 512)
        sT[(i >> 8) * T_STRIDE + (i & 255)] = g_T[i];
    for (int i = threadIdx.x; i < 1024 * 16; i += 512) {
        sU[(i >> 4) * UW_STRIDE + (i & 15)] = g_U[i];
        sW[(i >> 4) * UW_STRIDE + (i & 15)] = g_W[i];
    }
    __syncthreads();

    int warp = threadIdx.x >> 5;           // 0..15
    int lane = threadIdx.x & 31;
    int groups = B >> 5;                   // 8192 groups of 32 sorted entries
    int total_warps = gridDim.x << 4;
    int g0 = (blockIdx.x << 4) + warp;

    unsigned long long e_next = (g0 < groups) ? g_sorted[(g0 << 5) + lane] : 0ull;

    for (int g = g0; g < groups; g += total_warps) {
        unsigned long long e = e_next;
        int gn = g + total_warps;
        if (gn < groups) e_next = g_sorted[(gn << 5) + lane];

        unsigned mask = (unsigned)e;
        unsigned oidx = (unsigned)(e >> 32);

        // init: p[0..7] = U row (8 f32x2 pairs)
        unsigned long long p[8];
        {
            const ulonglong2* Up = (const ulonglong2*)(sU + (mask & 1023u) * UW_STRIDE);
            ulonglong2 a0 = Up[0], a1 = Up[1], a2 = Up[2], a3 = Up[3];
            p[0] = a0.x; p[1] = a0.y; p[2] = a1.x; p[3] = a1.y;
            p[4] = a2.x; p[5] = a2.y; p[6] = a3.x; p[7] = a3.y;
        }
        unsigned mm = mask >> 10;

        #pragma unroll
        for (int k = 0; k < 4; k++) {
            const ulonglong2* M = (const ulonglong2*)(sT + (k * 8 + (mm & 7u)) * T_STRIDE);
            mm >>= 3;
            unsigned long long acc[8];
            #pragma unroll
            for (int i = 0; i < 8; i++) {     // rows 2i and 2i+1
                float lo, hi;
                unpack2(p[i], lo, hi);
                unsigned long long bl = pack2(lo, lo);
                unsigned long long bh = pack2(hi, hi);
                ulonglong2 q0 = M[(2 * i) * 4 + 0];
                ulonglong2 q1 = M[(2 * i) * 4 + 1];
                ulonglong2 q2 = M[(2 * i) * 4 + 2];
                ulonglong2 q3 = M[(2 * i) * 4 + 3];
                if (i == 0) {
                    acc[0] = fmul2(bl, q0.x); acc[1] = fmul2(bl, q0.y);
                    acc[2] = fmul2(bl, q1.x); acc[3] = fmul2(bl, q1.y);
                    acc[4] = fmul2(bl, q2.x); acc[5] = fmul2(bl, q2.y);
                    acc[6] = fmul2(bl, q3.x); acc[7] = fmul2(bl, q3.y);
                } else {
                    acc[0] = ffma2(bl, q0.x, acc[0]); acc[1] = ffma2(bl, q0.y, acc[1]);
                    acc[2] = ffma2(bl, q1.x, acc[2]); acc[3] = ffma2(bl, q1.y, acc[3]);
                    acc[4] = ffma2(bl, q2.x, acc[4]); acc[5] = ffma2(bl, q2.y, acc[5]);
                    acc[6] = ffma2(bl, q3.x, acc[6]); acc[7] = ffma2(bl, q3.y, acc[7]);
                }
                ulonglong2 s0 = M[(2 * i + 1) * 4 + 0];
                ulonglong2 s1 = M[(2 * i + 1) * 4 + 1];
                ulonglong2 s2 = M[(2 * i + 1) * 4 + 2];
                ulonglong2 s3 = M[(2 * i + 1) * 4 + 3];
                acc[0] = ffma2(bh, s0.x, acc[0]); acc[1] = ffma2(bh, s0.y, acc[1]);
                acc[2] = ffma2(bh, s1.x, acc[2]); acc[3] = ffma2(bh, s1.y, acc[3]);
                acc[4] = ffma2(bh, s2.x, acc[4]); acc[5] = ffma2(bh, s2.y, acc[5]);
                acc[6] = ffma2(bh, s3.x, acc[6]); acc[7] = ffma2(bh, s3.y, acc[7]);
            }
            #pragma unroll
            for (int i = 0; i < 8; i++) p[i] = acc[i];
        }

        // final: dot(p, W[bits 22..31]) with two packed chains
        {
            const ulonglong2* Wp = (const ulonglong2*)(sW + mm * UW_STRIDE);
            ulonglong2 w0 = Wp[0], w1 = Wp[1], w2 = Wp[2], w3 = Wp[3];
            unsigned long long cA = fmul2(p[0], w0.x);
            unsigned long long cB = fmul2(p[1], w0.y);
            cA = ffma2(p[2], w1.x, cA);  cB = ffma2(p[3], w1.y, cB);
            cA = ffma2(p[4], w2.x, cA);  cB = ffma2(p[5], w2.y, cB);
            cA = ffma2(p[6], w3.x, cA);  cB = ffma2(p[7], w3.y, cB);
            cA = fadd2(cA, cB);
            float lo, hi;
            unpack2(cA, lo, hi);
            out[oidx] = lo + hi;
        }
    }
}

// ---------------------------------------------------------------------------
extern "C" void kernel_launch(void* const* d_in, const int* in_sizes, int n_in,
                              void* d_out, int out_size) {
    const int*   X  = (const int*)d_in[0];
    const float* cf = (const float*)d_in[1];
    const float* cm = (const float*)d_in[2];
    const float* cl = (const float*)d_in[3];
    float* out = (float*)d_out;

    int B = in_sizes[0] / 32;       // 262144
    int packB = B / 256;            // 1024 pack blocks (8 warps x 32 rows)

    zero_hist<<<4, 1024>>>();
    prep<<<packB + 132, 256>>>(X, cf, cm, cl, packB);
    scan_hist<<<1, 1024>>>();
    scatter<<<B / 256, 256>>>();

    int nsm = 148;
    cudaDeviceGetAttribute(&nsm, cudaDevAttrMultiProcessorCount, 0);

    cudaFuncSetAttribute(tt_main, cudaFuncAttributeMaxDynamicSharedMemorySize, SMEM_BYTES);
    tt_main<<<nsm, 512, SMEM_BYTES>>>(out, B);
}

// round 9
// speedup vs baseline: 1.4627x; 1.4627x over previous
#include <cuda_runtime.h>
#include <cstdint>

// Problem constants (fixed by dataset): B=262144, D=32, R=16
#define R 16
#define BATCH_MAX 262144

// Bit layout (bit i = X[b][i]):
//   bits 0..9   -> U table (1024): e_{x0}*F * M0..M8
//   bits 10..21 -> 4 mid groups of 3 bits: T_k = M_{9+3k}*M_{10+3k}*M_{11+3k}
//   bits 22..31 -> W table (1024): M21..M29 * last_{x31}
// Per batch: v = U[j0]; v = v @ T_k[idx_k] (k=0..3); out = dot(v, W[j1])
//
// Mid matrices at stride 260 floats (== 4 mod 32): LDS.128 phase bank-group
// = (idx + unit) mod 8, injective for idx in [0,8) -> conflict-free.

__device__ float    g_U[1024 * 16];
__device__ float    g_T[4 * 8 * 256];
__device__ float    g_W[1024 * 16];
__device__ unsigned g_masks[BATCH_MAX];

// ---------------------------------------------------------------------------
// Packed f32x2 helpers (sm_103a FFMA2 — only reachable via PTX fma.rn.f32x2)
// ---------------------------------------------------------------------------
__device__ __forceinline__ unsigned long long pack2(float a, float b) {
    unsigned long long r;
    asm("mov.b64 %0, {%1, %2};" : "=l"(r) : "f"(a), "f"(b));
    return r;
}
__device__ __forceinline__ void unpack2(unsigned long long p, float& a, float& b) {
    asm("mov.b64 {%0, %1}, %2;" : "=f"(a), "=f"(b) : "l"(p));
}
__device__ __forceinline__ unsigned long long ffma2(unsigned long long a,
                                                    unsigned long long b,
                                                    unsigned long long c) {
    unsigned long long d;
    asm("fma.rn.f32x2 %0, %1, %2, %3;" : "=l"(d) : "l"(a), "l"(b), "l"(c));
    return d;
}
__device__ __forceinline__ unsigned long long fmul2(unsigned long long a,
                                                    unsigned long long b) {
    unsigned long long d;
    asm("mul.rn.f32x2 %0, %1, %2;" : "=l"(d) : "l"(a), "l"(b));
    return d;
}
__device__ __forceinline__ unsigned long long fadd2(unsigned long long a,
                                                    unsigned long long b) {
    unsigned long long d;
    asm("add.rn.f32x2 %0, %1, %2;" : "=l"(d) : "l"(a), "l"(b));
    return d;
}

// ---------------------------------------------------------------------------
// Prep kernel: mask pack (coalesced ballot, 16-deep hoisted LDG) + builders.
//   blocks [0, packB)        : 8 warps x 32 rows each, coalesced ballot pack
//   blocks [packB, +64)      : U entries
//   blocks [packB+64, +128)  : W entries
//   blocks [packB+128, +132) : T group k
// ---------------------------------------------------------------------------
__global__ void prep(const int* __restrict__ X,
                     const float* __restrict__ cf,
                     const float* __restrict__ cm,
                     const float* __restrict__ cl,
                     int packB) {
    int bid = blockIdx.x;
    if (bid < packB) {
        int warp = threadIdx.x >> 5;
        int lane = threadIdx.x & 31;
        int base = (bid * 8 + warp) * 32;
        const int* xb = X + (long long)base * 32 + lane;
        unsigned mask = 0;
        #pragma unroll
        for (int h = 0; h < 2; h++) {
            int t[16];
            #pragma unroll
            for (int i = 0; i < 16; i++) t[i] = xb[(h * 16 + i) * 32];
            #pragma unroll
            for (int i = 0; i < 16; i++) {
                unsigned bm = __ballot_sync(0xffffffffu, t[i]);
                if (lane == h * 16 + i) mask = bm;
            }
        }
        g_masks[base + lane] = mask;   // lane i holds mask of row base+i
        return;
    }
    bid -= packB;
    if (bid < 64) {
        // U[j][s] = (e_{x0} F) * M_{0,b1} * ... * M_{8,b9}
        int gwarp = (bid * 256 + threadIdx.x) >> 5;   // 0..511
        int lane  = threadIdx.x & 31;
        int half  = lane >> 4;
        int s     = lane & 15;
        int j     = gwarp * 2 + half;                 // 0..1023
        float v = cf[s * 2 + (j & 1)];
        for (int i = 0; i < 9; i++) {
            int b = (j >> (i + 1)) & 1;
            float nv = 0.f;
            #pragma unroll
            for (int r = 0; r < 16; r++) {
                float vr = __shfl_sync(0xffffffffu, v, (half << 4) + r);
                nv += vr * cm[((i * 16 + r) * 16 + s) * 2 + b];
            }
            v = nv;
        }
        g_U[j * 16 + s] = v;
    } else if (bid < 128) {
        // W[j][r] = (M_{21,b0} * ... * M_{29,b8} * lastcol_{b9})[r]
        int gwarp = ((bid - 64) * 256 + threadIdx.x) >> 5;
        int lane  = threadIdx.x & 31;
        int half  = lane >> 4;
        int r     = lane & 15;
        int j     = gwarp * 2 + half;
        float v = cl[r * 2 + ((j >> 9) & 1)];
        for (int i = 8; i >= 0; i--) {
            int c = 21 + i;
            int b = (j >> i) & 1;
            float nv = 0.f;
            #pragma unroll
            for (int t = 0; t < 16; t++) {
                float vt = __shfl_sync(0xffffffffu, v, (half << 4) + t);
                nv += cm[((c * 16 + r) * 16 + t) * 2 + b] * vt;
            }
            v = nv;
        }
        g_W[j * 16 + r] = v;
    } else {
        // T_k[idx] = M_{9+3k,b0} * M_{10+3k,b1} * M_{11+3k,b2}
        if (threadIdx.x >= 128) return;
        int k   = bid - 128;
        int idx = threadIdx.x >> 4;
        int s   = threadIdx.x & 15;
        float v[R], nv[R];
        int c2 = 9 + 3 * k + 2;
        int b2 = (idx >> 2) & 1;
        #pragma unroll
        for (int t = 0; t < R; t++) v[t] = cm[((c2 * R + t) * R + s) * 2 + b2];
        for (int jj = 1; jj >= 0; jj--) {
            int c = 9 + 3 * k + jj;
            int b = (idx >> jj) & 1;
            #pragma unroll
            for (int r = 0; r < R; r++) {
                float acc = 0.f;
                #pragma unroll
                for (int t = 0; t < R; t++)
                    acc += cm[((c * R + r) * R + t) * 2 + b] * v[t];
                nv[r] = acc;
            }
            #pragma unroll
            for (int r = 0; r < R; r++) v[r] = nv[r];
        }
        #pragma unroll
        for (int r = 0; r < R; r++)
            g_T[(k * 8 + idx) * 256 + r * R + s] = v[r];
    }
}

// ---------------------------------------------------------------------------
// Main kernel: 768 threads/block (1 block/SM due to smem) -> 24 warps to
// fill the LDS crossbar; two-pass matvec keeps live regs within the ~84-reg
// budget (no spills). Masks precomputed in g_masks, prefetched 1 group ahead.
// ---------------------------------------------------------------------------
#define T_STRIDE 260
#define UW_STRIDE 20
#define ST_FLOATS (4 * 8 * T_STRIDE)
#define SUW_FLOATS (1024 * UW_STRIDE)
#define SMEM_FLOATS (ST_FLOATS + 2 * SUW_FLOATS)
#define SMEM_BYTES (SMEM_FLOATS * 4)

#define NTHR 768
#define NWARP (NTHR / 32)

extern __shared__ float sm_buf[];

__global__ __launch_bounds__(NTHR, 1) void tt_main(float* __restrict__ out, int B) {
    float* sT = sm_buf;
    float* sU = sm_buf + ST_FLOATS;
    float* sW = sU + SUW_FLOATS;

    for (int i = threadIdx.x; i < 4 * 8 * 256; i += NTHR)
        sT[(i >> 8) * T_STRIDE + (i & 255)] = g_T[i];
    for (int i = threadIdx.x; i < 1024 * 16; i += NTHR) {
        sU[(i >> 4) * UW_STRIDE + (i & 15)] = g_U[i];
        sW[(i >> 4) * UW_STRIDE + (i & 15)] = g_W[i];
    }
    __syncthreads();

    int warp = threadIdx.x >> 5;               // 0..NWARP-1
    int lane = threadIdx.x & 31;
    int groups = B >> 5;                       // 8192 groups of 32 batches
    int total_warps = gridDim.x * NWARP;
    int g0 = blockIdx.x * NWARP + warp;

    unsigned mask_next = (g0 < groups) ? g_masks[(g0 << 5) + lane] : 0u;

    for (int g = g0; g < groups; g += total_warps) {
        unsigned mask = mask_next;
        int gn = g + total_warps;
        if (gn < groups) mask_next = g_masks[(gn << 5) + lane];
        int base = g << 5;

        // init: p[0..7] = U row (8 f32x2 pairs)
        unsigned long long p[8];
        {
            const ulonglong2* Up = (const ulonglong2*)(sU + (mask & 1023u) * UW_STRIDE);
            ulonglong2 a0 = Up[0], a1 = Up[1], a2 = Up[2], a3 = Up[3];
            p[0] = a0.x; p[1] = a0.y; p[2] = a1.x; p[3] = a1.y;
            p[4] = a2.x; p[5] = a2.y; p[6] = a3.x; p[7] = a3.y;
        }
        unsigned mm = mask >> 10;

        #pragma unroll
        for (int k = 0; k < 4; k++) {
            const ulonglong2* M = (const ulonglong2*)(sT + (k * 8 + (mm & 7u)) * T_STRIDE);
            mm >>= 3;

            // Pass A: output cols 0..7 (units 0,1 of each row)
            unsigned long long a0, a1, a2, a3;
            #pragma unroll
            for (int i = 0; i < 8; i++) {
                float lo, hi;
                unpack2(p[i], lo, hi);
                unsigned long long bl = pack2(lo, lo);
                unsigned long long bh = pack2(hi, hi);
                ulonglong2 q0 = M[(2 * i) * 4 + 0];
                ulonglong2 q1 = M[(2 * i) * 4 + 1];
                ulonglong2 s0 = M[(2 * i + 1) * 4 + 0];
                ulonglong2 s1 = M[(2 * i + 1) * 4 + 1];
                if (i == 0) {
                    a0 = fmul2(bl, q0.x); a1 = fmul2(bl, q0.y);
                    a2 = fmul2(bl, q1.x); a3 = fmul2(bl, q1.y);
                } else {
                    a0 = ffma2(bl, q0.x, a0); a1 = ffma2(bl, q0.y, a1);
                    a2 = ffma2(bl, q1.x, a2); a3 = ffma2(bl, q1.y, a3);
                }
                a0 = ffma2(bh, s0.x, a0); a1 = ffma2(bh, s0.y, a1);
                a2 = ffma2(bh, s1.x, a2); a3 = ffma2(bh, s1.y, a3);
            }

            // Pass B: output cols 8..15 (units 2,3 of each row)
            unsigned long long b0, b1, b2, b3;
            #pragma unroll
            for (int i = 0; i < 8; i++) {
                float lo, hi;
                unpack2(p[i], lo, hi);
                unsigned long long bl = pack2(lo, lo);
                unsigned long long bh = pack2(hi, hi);
                ulonglong2 q2 = M[(2 * i) * 4 + 2];
                ulonglong2 q3 = M[(2 * i) * 4 + 3];
                ulonglong2 s2 = M[(2 * i + 1) * 4 + 2];
                ulonglong2 s3 = M[(2 * i + 1) * 4 + 3];
                if (i == 0) {
                    b0 = fmul2(bl, q2.x); b1 = fmul2(bl, q2.y);
                    b2 = fmul2(bl, q3.x); b3 = fmul2(bl, q3.y);
                } else {
                    b0 = ffma2(bl, q2.x, b0); b1 = ffma2(bl, q2.y, b1);
                    b2 = ffma2(bl, q3.x, b2); b3 = ffma2(bl, q3.y, b3);
                }
                b0 = ffma2(bh, s2.x, b0); b1 = ffma2(bh, s2.y, b1);
                b2 = ffma2(bh, s3.x, b2); b3 = ffma2(bh, s3.y, b3);
            }

            p[0] = a0; p[1] = a1; p[2] = a2; p[3] = a3;
            p[4] = b0; p[5] = b1; p[6] = b2; p[7] = b3;
        }

        // final: dot(p, W[bits 22..31]) with two packed chains
        {
            const ulonglong2* Wp = (const ulonglong2*)(sW + mm * UW_STRIDE);
            ulonglong2 w0 = Wp[0], w1 = Wp[1], w2 = Wp[2], w3 = Wp[3];
            unsigned long long cA = fmul2(p[0], w0.x);
            unsigned long long cB = fmul2(p[1], w0.y);
            cA = ffma2(p[2], w1.x, cA);  cB = ffma2(p[3], w1.y, cB);
            cA = ffma2(p[4], w2.x, cA);  cB = ffma2(p[5], w2.y, cB);
            cA = ffma2(p[6], w3.x, cA);  cB = ffma2(p[7], w3.y, cB);
            cA = fadd2(cA, cB);
            float lo, hi;
            unpack2(cA, lo, hi);
            out[base + lane] = lo + hi;
        }
    }
}

// ---------------------------------------------------------------------------
extern "C" void kernel_launch(void* const* d_in, const int* in_sizes, int n_in,
                              void* d_out, int out_size) {
    const int*   X  = (const int*)d_in[0];
    const float* cf = (const float*)d_in[1];
    const float* cm = (const float*)d_in[2];
    const float* cl = (const float*)d_in[3];
    float* out = (float*)d_out;

    int B = in_sizes[0] / 32;       // 262144
    int packB = B / 256;            // 1024 pack blocks (8 warps x 32 rows)

    prep<<<packB + 132, 256>>>(X, cf, cm, cl, packB);

    int nsm = 148;
    cudaDeviceGetAttribute(&nsm, cudaDevAttrMultiProcessorCount, 0);

    cudaFuncSetAttribute(tt_main, cudaFuncAttributeMaxDynamicSharedMemorySize, SMEM_BYTES);
    tt_main<<<nsm, NTHR, SMEM_BYTES>>>(out, B);
}

// round 10
// speedup vs baseline: 1.7437x; 1.1921x over previous
#include <cuda_runtime.h>
#include <cuda_fp16.h>
#include <cstdint>

// Problem constants (fixed by dataset): B=262144, D=32, R=16
#define R 16
#define BATCH_MAX 262144

// Bit layout (bit i = X[b][i]):
//   bits 0..9   -> U table (1024 fp32): e_{x0}*F * M0..M8
//   bits 10..15 -> pair table P0 (64 fp16 mats): M9*...*M14
//   bits 16..21 -> pair table P1 (64 fp16 mats): M15*...*M20
//   bits 22..31 -> W table (1024 fp32): M21..M29 * last_{x31}
// Per batch: v = U[j0]; v = v @ P0[j1]; v = v @ P1[j2]; out = dot(v, W[j3])

__device__ float    g_U[1024 * 16];
__device__ __half   g_P[2 * 64 * 256];
__device__ float    g_W[1024 * 16];
__device__ unsigned g_masks[BATCH_MAX];

// ---------------------------------------------------------------------------
// Packed f32x2 helpers (sm_103a FFMA2 — only reachable via PTX fma.rn.f32x2)
// ---------------------------------------------------------------------------
__device__ __forceinline__ unsigned long long pack2(float a, float b) {
    unsigned long long r;
    asm("mov.b64 %0, {%1, %2};" : "=l"(r) : "f"(a), "f"(b));
    return r;
}
__device__ __forceinline__ void unpack2(unsigned long long p, float& a, float& b) {
    asm("mov.b64 {%0, %1}, %2;" : "=f"(a), "=f"(b) : "l"(p));
}
__device__ __forceinline__ unsigned long long ffma2(unsigned long long a,
                                                    unsigned long long b,
                                                    unsigned long long c) {
    unsigned long long d;
    asm("fma.rn.f32x2 %0, %1, %2, %3;" : "=l"(d) : "l"(a), "l"(b), "l"(c));
    return d;
}
__device__ __forceinline__ unsigned long long fmul2(unsigned long long a,
                                                    unsigned long long b) {
    unsigned long long d;
    asm("mul.rn.f32x2 %0, %1, %2;" : "=l"(d) : "l"(a), "l"(b));
    return d;
}
__device__ __forceinline__ unsigned long long fadd2(unsigned long long a,
                                                    unsigned long long b) {
    unsigned long long d;
    asm("add.rn.f32x2 %0, %1, %2;" : "=l"(d) : "l"(a), "l"(b));
    return d;
}
// fp16 pair (u32) -> f32x2 (u64)
__device__ __forceinline__ unsigned long long h2f2(unsigned h) {
    unsigned long long d;
    asm("{\n\t.reg .b16 l, hh;\n\t.reg .f32 f0, f1;\n\t"
        "mov.b32 {l, hh}, %1;\n\t"
        "cvt.f32.f16 f0, l;\n\t"
        "cvt.f32.f16 f1, hh;\n\t"
        "mov.b64 %0, {f0, f1};\n\t}" : "=l"(d) : "r"(h));
    return d;
}

// ---------------------------------------------------------------------------
// Prep kernel: mask pack + builders.
//   blocks [0, packB)        : 8 warps x 32 rows, coalesced ballot pack
//   blocks [packB, +64)      : U entries (warp-collaborative)
//   blocks [packB+64, +128)  : W entries
//   blocks [packB+128, +136) : P pair-product entries (fp16)
// ---------------------------------------------------------------------------
__global__ void prep(const int* __restrict__ X,
                     const float* __restrict__ cf,
                     const float* __restrict__ cm,
                     const float* __restrict__ cl,
                     int packB) {
    int bid = blockIdx.x;
    if (bid < packB) {
        int warp = threadIdx.x >> 5;
        int lane = threadIdx.x & 31;
        int base = (bid * 8 + warp) * 32;
        const int* xb = X + (long long)base * 32 + lane;
        unsigned mask = 0;
        #pragma unroll
        for (int h = 0; h < 2; h++) {
            int t[16];
            #pragma unroll
            for (int i = 0; i < 16; i++) t[i] = xb[(h * 16 + i) * 32];
            #pragma unroll
            for (int i = 0; i < 16; i++) {
                unsigned bm = __ballot_sync(0xffffffffu, t[i]);
                if (lane == h * 16 + i) mask = bm;
            }
        }
        g_masks[base + lane] = mask;
        return;
    }
    bid -= packB;
    if (bid < 64) {
        // U[j][s] = (e_{x0} F) * M_{0,b1} * ... * M_{8,b9}
        int gwarp = (bid * 256 + threadIdx.x) >> 5;   // 0..511
        int lane  = threadIdx.x & 31;
        int half  = lane >> 4;
        int s     = lane & 15;
        int j     = gwarp * 2 + half;                 // 0..1023
        float v = cf[s * 2 + (j & 1)];
        for (int i = 0; i < 9; i++) {
            int b = (j >> (i + 1)) & 1;
            float nv = 0.f;
            #pragma unroll
            for (int r = 0; r < 16; r++) {
                float vr = __shfl_sync(0xffffffffu, v, (half << 4) + r);
                nv += vr * cm[((i * 16 + r) * 16 + s) * 2 + b];
            }
            v = nv;
        }
        g_U[j * 16 + s] = v;
    } else if (bid < 128) {
        // W[j][r] = (M_{21,b0} * ... * M_{29,b8} * lastcol_{b9})[r]
        int gwarp = ((bid - 64) * 256 + threadIdx.x) >> 5;
        int lane  = threadIdx.x & 31;
        int half  = lane >> 4;
        int r     = lane & 15;
        int j     = gwarp * 2 + half;
        float v = cl[r * 2 + ((j >> 9) & 1)];
        for (int i = 8; i >= 0; i--) {
            int c = 21 + i;
            int b = (j >> i) & 1;
            float nv = 0.f;
            #pragma unroll
            for (int t = 0; t < 16; t++) {
                float vt = __shfl_sync(0xffffffffu, v, (half << 4) + t);
                nv += cm[((c * 16 + r) * 16 + t) * 2 + b] * vt;
            }
            v = nv;
        }
        g_W[j * 16 + r] = v;
    } else {
        // P[g][idx] = M_{9+6g,b0} * ... * M_{14+6g,b5}, rounded to fp16.
        // Thread per (idx, col s): column s via right-to-left matvecs.
        int gp  = bid - 128;              // 0..7
        int g   = gp >> 2;                // 0..1
        int idx = (gp & 3) * 16 + (threadIdx.x >> 4);   // 0..63
        int s   = threadIdx.x & 15;
        float v[R], nv[R];
        int c5 = 9 + 6 * g + 5;
        int b5 = (idx >> 5) & 1;
        #pragma unroll
        for (int t = 0; t < R; t++) v[t] = cm[((c5 * R + t) * R + s) * 2 + b5];
        for (int jj = 4; jj >= 0; jj--) {
            int c = 9 + 6 * g + jj;
            int b = (idx >> jj) & 1;
            #pragma unroll
            for (int r = 0; r < R; r++) {
                float acc = 0.f;
                #pragma unroll
                for (int t = 0; t < R; t++)
                    acc += cm[((c * R + r) * R + t) * 2 + b] * v[t];
                nv[r] = acc;
            }
            #pragma unroll
            for (int r = 0; r < R; r++) v[r] = nv[r];
        }
        #pragma unroll
        for (int r = 0; r < R; r++)
            g_P[(g * 64 + idx) * 256 + r * R + s] = __float2half_rn(v[r]);
    }
}

// ---------------------------------------------------------------------------
// Main kernel: 512 threads/block, 1 block/SM (smem) -> ~128 reg budget.
// smem: sU[1024*20 f32], sW[1024*20 f32], sP[128 mats * 264 halves]
// (264-half = 528B = 33 x 16B units -> unit bank-group = (idx + u) mod 8).
// ---------------------------------------------------------------------------
#define UW_STRIDE 20
#define SUW_FLOATS (1024 * UW_STRIDE)
#define P_STRIDE_H 264
#define SP_HALFS (128 * P_STRIDE_H)
#define SMEM_BYTES (2 * SUW_FLOATS * 4 + SP_HALFS * 2)   // 163840 + 67584 = 231424

#define NTHR 512
#define NWARP (NTHR / 32)

extern __shared__ float sm_buf[];

__global__ __launch_bounds__(NTHR, 1) void tt_main(float* __restrict__ out, int B) {
    float*  sU = sm_buf;
    float*  sW = sm_buf + SUW_FLOATS;
    __half* sP = (__half*)(sm_buf + 2 * SUW_FLOATS);

    for (int i = threadIdx.x; i < 1024 * 16; i += NTHR) {
        sU[(i >> 4) * UW_STRIDE + (i & 15)] = g_U[i];
        sW[(i >> 4) * UW_STRIDE + (i & 15)] = g_W[i];
    }
    {   // stage P as u32 pairs (both halves land in the same matrix block)
        const unsigned* gp32 = (const unsigned*)g_P;
        unsigned* sp32base = (unsigned*)sP;   // only for typing; use indexed halves
        (void)sp32base;
        for (int i = threadIdx.x; i < (2 * 64 * 256) / 2; i += NTHR) {
            int e = i << 1;                   // even half index
            unsigned* dst = (unsigned*)(sP + (e >> 8) * P_STRIDE_H + (e & 255));
            *dst = gp32[i];
        }
    }
    __syncthreads();

    int warp = threadIdx.x >> 5;
    int lane = threadIdx.x & 31;
    int groups = B >> 5;                       // 8192 groups of 32 batches
    int total_warps = gridDim.x * NWARP;
    int g0 = blockIdx.x * NWARP + warp;

    unsigned mask_next = (g0 < groups) ? g_masks[(g0 << 5) + lane] : 0u;

    for (int g = g0; g < groups; g += total_warps) {
        unsigned mask = mask_next;
        int gn = g + total_warps;
        if (gn < groups) mask_next = g_masks[(gn << 5) + lane];
        int base = g << 5;

        // init: p[0..7] = U row (8 f32x2 pairs)
        unsigned long long p[8];
        {
            const ulonglong2* Up = (const ulonglong2*)(sU + (mask & 1023u) * UW_STRIDE);
            ulonglong2 a0 = Up[0], a1 = Up[1], a2 = Up[2], a3 = Up[3];
            p[0] = a0.x; p[1] = a0.y; p[2] = a1.x; p[3] = a1.y;
            p[4] = a2.x; p[5] = a2.y; p[6] = a3.x; p[7] = a3.y;
        }

        // two fp16 pair-product stages
        #pragma unroll
        for (int st = 0; st < 2; st++) {
            unsigned idx = (mask >> (10 + 6 * st)) & 63u;
            const uint4* M = (const uint4*)(sP + (st * 64 + idx) * P_STRIDE_H);
            unsigned long long acc[8];
            #pragma unroll
            for (int i = 0; i < 8; i++) {        // rows 2i and 2i+1
                float lo, hi;
                unpack2(p[i], lo, hi);
                unsigned long long bl = pack2(lo, lo);
                unsigned long long bh = pack2(hi, hi);
                uint4 ra = M[4 * i + 0];         // row 2i   cols 0..7
                uint4 rb = M[4 * i + 1];         // row 2i   cols 8..15
                uint4 rc = M[4 * i + 2];         // row 2i+1 cols 0..7
                uint4 rd = M[4 * i + 3];         // row 2i+1 cols 8..15
                if (i == 0) {
                    acc[0] = fmul2(bl, h2f2(ra.x)); acc[1] = fmul2(bl, h2f2(ra.y));
                    acc[2] = fmul2(bl, h2f2(ra.z)); acc[3] = fmul2(bl, h2f2(ra.w));
                    acc[4] = fmul2(bl, h2f2(rb.x)); acc[5] = fmul2(bl, h2f2(rb.y));
                    acc[6] = fmul2(bl, h2f2(rb.z)); acc[7] = fmul2(bl, h2f2(rb.w));
                } else {
                    acc[0] = ffma2(bl, h2f2(ra.x), acc[0]); acc[1] = ffma2(bl, h2f2(ra.y), acc[1]);
                    acc[2] = ffma2(bl, h2f2(ra.z), acc[2]); acc[3] = ffma2(bl, h2f2(ra.w), acc[3]);
                    acc[4] = ffma2(bl, h2f2(rb.x), acc[4]); acc[5] = ffma2(bl, h2f2(rb.y), acc[5]);
                    acc[6] = ffma2(bl, h2f2(rb.z), acc[6]); acc[7] = ffma2(bl, h2f2(rb.w), acc[7]);
                }
                acc[0] = ffma2(bh, h2f2(rc.x), acc[0]); acc[1] = ffma2(bh, h2f2(rc.y), acc[1]);
                acc[2] = ffma2(bh, h2f2(rc.z), acc[2]); acc[3] = ffma2(bh, h2f2(rc.w), acc[3]);
                acc[4] = ffma2(bh, h2f2(rd.x), acc[4]); acc[5] = ffma2(bh, h2f2(rd.y), acc[5]);
                acc[6] = ffma2(bh, h2f2(rd.z), acc[6]); acc[7] = ffma2(bh, h2f2(rd.w), acc[7]);
            }
            #pragma unroll
            for (int i = 0; i < 8; i++) p[i] = acc[i];
        }

        // final: dot(p, W[bits 22..31]) with two packed chains
        {
            const ulonglong2* Wp = (const ulonglong2*)(sW + (mask >> 22) * UW_STRIDE);
            ulonglong2 w0 = Wp[0], w1 = Wp[1], w2 = Wp[2], w3 = Wp[3];
            unsigned long long cA = fmul2(p[0], w0.x);
            unsigned long long cB = fmul2(p[1], w0.y);
            cA = ffma2(p[2], w1.x, cA);  cB = ffma2(p[3], w1.y, cB);
            cA = ffma2(p[4], w2.x, cA);  cB = ffma2(p[5], w2.y, cB);
            cA = ffma2(p[6], w3.x, cA);  cB = ffma2(p[7], w3.y, cB);
            cA = fadd2(cA, cB);
            float lo, hi;
            unpack2(cA, lo, hi);
            out[base + lane] = lo + hi;
        }
    }
}

// ---------------------------------------------------------------------------
extern "C" void kernel_launch(void* const* d_in, const int* in_sizes, int n_in,
                              void* d_out, int out_size) {
    const int*   X  = (const int*)d_in[0];
    const float* cf = (const float*)d_in[1];
    const float* cm = (const float*)d_in[2];
    const float* cl = (const float*)d_in[3];
    float* out = (float*)d_out;

    int B = in_sizes[0] / 32;       // 262144
    int packB = B / 256;            // 1024 pack blocks

    prep<<<packB + 136, 256>>>(X, cf, cm, cl, packB);

    int nsm = 148;
    cudaDeviceGetAttribute(&nsm, cudaDevAttrMultiProcessorCount, 0);

    cudaFuncSetAttribute(tt_main, cudaFuncAttributeMaxDynamicSharedMemorySize, SMEM_BYTES);
    tt_main<<<nsm, NTHR, SMEM_BYTES>>>(out, B);
}